// round 12
// baseline (speedup 1.0000x reference)
#include <cuda_runtime.h>
#include <cuda_fp16.h>
#include <cstdint>
#include <cstddef>

#define IN 2048
#define DIM 128
#define NBATCH 4
#define ITERS 50
#define KELEMS (NBATCH*IN*IN)   // 16,777,216 elements

#define SKT 512                  // sinkhorn threads (16 warps)

// dynamic smem: v (4KB) + per-warp partials (16 x 4KB = 64KB) + ring (128KB)
#define SMEM_V_BYTES 4096
#define SMEM_PART_BYTES (16 * IN * 2)
#define SMEM_RING_BYTES (16 * 4 * 2048)
#define SMEM_TOTAL_BYTES (SMEM_V_BYTES + SMEM_PART_BYTES + SMEM_RING_BYTES)

// ---------------- scratch (static device globals: allocation-free) ----------
__device__ __half g_K1[KELEMS];                // K for OT1 (src,tgt)  33.5 MB
__device__ __half g_K2[KELEMS];                // K for OT2 (tgt,gen)  33.5 MB
__device__ float g_A[2][3][NBATCH*IN];         // triple-buffered column accumulators
__device__ float g_u[2][NBATCH*IN];            // final u per OT
__device__ float g_vfin[2][NBATCH*IN];         // final v per OT
__device__ unsigned g_bar8[8 * 32];            // per-(segment,OT) barrier counters

// exp(1 - c) for c in [-1,1]; degree-9 Taylor of exp(t), t=-c, times e.
__device__ __forceinline__ float exp_shift(float c){
    float t = -c;
    float p = 2.7557319e-6f;
    p = fmaf(p, t, 2.4801587e-5f);
    p = fmaf(p, t, 1.9841270e-4f);
    p = fmaf(p, t, 1.3888889e-3f);
    p = fmaf(p, t, 8.3333333e-3f);
    p = fmaf(p, t, 4.1666667e-2f);
    p = fmaf(p, t, 1.6666667e-1f);
    p = fmaf(p, t, 0.5f);
    p = fmaf(p, t, 1.0f);
    p = fmaf(p, t, 1.0f);
    return 2.7182818284f * p;
}

__device__ __forceinline__ void cp16(uint32_t dst, const void* src){
    asm volatile("cp.async.cg.shared.global [%0], [%1], 16;" :: "r"(dst), "l"(src));
}

// ---------------- init ------------------------------------------------------
__global__ void init_kernel(float* out){
    int idx = blockIdx.x * blockDim.x + threadIdx.x;
    if (idx == 0) out[0] = 0.0f;
    if (idx < 8 * 32) g_bar8[idx] = 0u;
    if (idx < NBATCH*IN){
        g_A[0][0][idx] = 1.0f;   // epoch 0 reads buf0 => v = ones
        g_A[1][0][idx] = 1.0f;
        g_A[0][1][idx] = 0.0f;   // epoch 0 accumulates into buf1
        g_A[1][1][idx] = 0.0f;
        g_A[0][2][idx] = 0.0f;
        g_A[1][2][idx] = 0.0f;
    }
}

// dummy launch: keeps ncu's -s 5 -c 1 profile window on sinkhorn_kernel
__global__ void profile_pad_kernel(){ }

// ---------------- tensor-core GEMM + exp -> fp16 K --------------------------
#define SA 72   // smem row stride in halves

__global__ __launch_bounds__(256) void gemm_exp_hmma(
        const float* __restrict__ src, const float* __restrict__ tgt,
        const float* __restrict__ gen){
    int ot = blockIdx.z >> 2;
    int b  = blockIdx.z & 3;
    const float* q  = (ot ? tgt : src) + (size_t)b * IN * DIM;
    const float* kk = (ot ? gen : tgt) + (size_t)b * IN * DIM;
    __half* Kout    = (ot ? g_K2 : g_K1) + (size_t)b * IN * IN;
    int i0 = blockIdx.y * 128;
    int o0 = blockIdx.x * 128;

    __shared__ __half As[128 * SA];
    __shared__ __half Bs[128 * SA];

    int tid  = threadIdx.x;
    int lane = tid & 31, warp = tid >> 5;
    int wr = warp >> 2, wc = warp & 3;

    float c[4][4][4];
    #pragma unroll
    for (int mi = 0; mi < 4; mi++)
        #pragma unroll
        for (int ni = 0; ni < 4; ni++)
            #pragma unroll
            for (int j = 0; j < 4; j++) c[mi][ni][j] = 0.f;

    for (int dc = 0; dc < DIM; dc += 64){
        #pragma unroll
        for (int l = 0; l < 8; l++){
            int fidx = tid + 256 * l;       // 0..2047
            int r  = fidx >> 4;
            int f4 = (fidx & 15) << 2;
            float4 va = *(const float4*)(q  + (size_t)(i0 + r) * DIM + dc + f4);
            float4 vb = *(const float4*)(kk + (size_t)(o0 + r) * DIM + dc + f4);
            __half2 a0 = __floats2half2_rn(va.x, va.y);
            __half2 a1 = __floats2half2_rn(va.z, va.w);
            __half2 b0 = __floats2half2_rn(vb.x, vb.y);
            __half2 b1 = __floats2half2_rn(vb.z, vb.w);
            uint2 pa = make_uint2(*(uint32_t*)&a0, *(uint32_t*)&a1);
            uint2 pb = make_uint2(*(uint32_t*)&b0, *(uint32_t*)&b1);
            *(uint2*)&As[r * SA + f4] = pa;
            *(uint2*)&Bs[r * SA + f4] = pb;
        }
        __syncthreads();

        #pragma unroll
        for (int ks = 0; ks < 4; ks++){
            int k0 = ks * 16;
            uint32_t af[4][4], bf[4][2];
            #pragma unroll
            for (int mi = 0; mi < 4; mi++){
                int row = wr * 64 + mi * 16 + (lane & 7) + ((lane >> 3) & 1) * 8;
                int col = k0 + (lane >> 4) * 8;
                uint32_t ad = (uint32_t)__cvta_generic_to_shared(&As[row * SA + col]);
                asm volatile("ldmatrix.sync.aligned.m8n8.x4.shared.b16 {%0,%1,%2,%3}, [%4];"
                    : "=r"(af[mi][0]), "=r"(af[mi][1]), "=r"(af[mi][2]), "=r"(af[mi][3])
                    : "r"(ad));
            }
            #pragma unroll
            for (int ni = 0; ni < 4; ni++){
                int rowb = wc * 32 + ni * 8 + (lane & 7);
                int colb = k0 + ((lane >> 3) & 1) * 8;
                uint32_t ad = (uint32_t)__cvta_generic_to_shared(&Bs[rowb * SA + colb]);
                asm volatile("ldmatrix.sync.aligned.m8n8.x2.shared.b16 {%0,%1}, [%2];"
                    : "=r"(bf[ni][0]), "=r"(bf[ni][1])
                    : "r"(ad));
            }
            #pragma unroll
            for (int mi = 0; mi < 4; mi++)
                #pragma unroll
                for (int ni = 0; ni < 4; ni++){
                    asm volatile(
                        "mma.sync.aligned.m16n8k16.row.col.f32.f16.f16.f32 "
                        "{%0,%1,%2,%3}, {%4,%5,%6,%7}, {%8,%9}, {%0,%1,%2,%3};"
                        : "+f"(c[mi][ni][0]), "+f"(c[mi][ni][1]),
                          "+f"(c[mi][ni][2]), "+f"(c[mi][ni][3])
                        : "r"(af[mi][0]), "r"(af[mi][1]), "r"(af[mi][2]), "r"(af[mi][3]),
                          "r"(bf[ni][0]), "r"(bf[ni][1]));
                }
        }
        __syncthreads();
    }

    // epilogue: exp(1-c), diag = e^-10, write half2 pairs directly
    int rbase = i0 + wr * 64 + (lane >> 2);
    int cbase = o0 + wc * 32 + (lane & 3) * 2;
    #pragma unroll
    for (int mi = 0; mi < 4; mi++){
        #pragma unroll
        for (int ni = 0; ni < 4; ni++){
            int ce = cbase + ni * 8;
            #pragma unroll
            for (int h = 0; h < 2; h++){
                int re = rbase + mi * 16 + h * 8;
                float fx = (re == ce    ) ? 4.5399930e-5f : exp_shift(c[mi][ni][h*2+0]);
                float fy = (re == ce + 1) ? 4.5399930e-5f : exp_shift(c[mi][ni][h*2+1]);
                *(__half2*)(Kout + (size_t)re * IN + ce) = __floats2half2_rn(fx, fy);
            }
        }
    }
}

// ---------------- persistent fused Sinkhorn (cp.async pipelined) ------------
// 512 threads, 16 warps, warp-per-row. Each warp streams its rows through a
// PRIVATE 4-slot ring of half-row (2KB) smem chunks via cp.async.cg, always
// 3 chunks ahead (wait_group 3). Lane-private data flow => no inner-loop
// barriers. v in registers all epoch; acc in registers; single K pass.
__global__ __launch_bounds__(SKT, 1) void sinkhorn_kernel(int nblocks){
    extern __shared__ __align__(16) char dynsm[];
    __half* v_sh = (__half*)dynsm;                               // 4 KB
    __half* part = (__half*)(dynsm + SMEM_V_BYTES);              // 64 KB
    char*   ring = dynsm + SMEM_V_BYTES + SMEM_PART_BYTES;       // 128 KB
    uint32_t ring32 = (uint32_t)__cvta_generic_to_shared(ring);

    int tid  = threadIdx.x;
    int lane = tid & 31, warp = tid >> 5;
    int w4 = warp * 4;

    int seg = blockIdx.x & 3;                       // batch segment 0..3
    int bis = blockIdx.x >> 2;
    int nbs = (nblocks - seg + 3) >> 2;             // blocks in this segment
    int r0 = (int)(((long)IN * bis) / nbs);
    int r1 = (int)(((long)IN * (bis + 1)) / nbs);

    int rbase = r0 + warp;
    int nrows = (rbase < r1) ? ((r1 - rbase + 15) >> 4) : 0;
    int n_chunks = nrows * 2;

    for (int e = 0; e < ITERS; e++){
        for (int ot = 0; ot < 2; ot++){
            unsigned* mybar = &g_bar8[(seg * 2 + ot) * 32];
            // wait for ALL blocks to have flushed epoch e-1 of this OT
            if (e > 0){
                if (tid == 0){
                    volatile unsigned* vb = mybar;
                    unsigned target = (unsigned)e * (unsigned)nbs;
                    while (*vb < target) { __nanosleep(32); }
                }
                __syncthreads();
            }
            const __half* Kb = (ot ? g_K2 : g_K1) + (size_t)seg * IN * IN;
            const float* Ar = &g_A[ot][e % 3][seg * IN];
            float*       Az = &g_A[ot][(e + 2) % 3][seg * IN];
            for (int o = tid; o < IN; o += SKT){
                float v = 1.0f / __ldcg(Ar + o);
                v_sh[o] = __float2half_rn(v);
                Az[o] = 0.0f;                        // idempotent zero for next epoch
            }
            __syncthreads();

            // v -> registers for the whole epoch: vr[h*4+j] = V4[h*128+j*32+lane]
            const uint4* V4 = (const uint4*)v_sh;
            uint4 vr[8];
            #pragma unroll
            for (int t = 0; t < 8; t++)
                vr[t] = V4[(t >> 2) * 128 + (t & 3) * 32 + lane];

            __half2 acc[32];
            #pragma unroll
            for (int j = 0; j < 32; j++) acc[j] = __float2half2_rn(0.f);

            if (n_chunks > 0){
                // prologue: issue chunks 0,1,2 (one commit group each)
                #pragma unroll
                for (int ci = 0; ci < 3; ci++){
                    int cc = (ci < n_chunks) ? ci : (n_chunks - 1);
                    const char* src = (const char*)(Kb + (size_t)(rbase + (cc >> 1) * 16) * IN
                                                    + (cc & 1) * 1024) + lane * 16;
                    uint32_t dst = ring32 + (uint32_t)((w4 + ci) * 2048) + lane * 16;
                    cp16(dst,        src);
                    cp16(dst +  512, src +  512);
                    cp16(dst + 1024, src + 1024);
                    cp16(dst + 1536, src + 1536);
                    asm volatile("cp.async.commit_group;" ::: "memory");
                }

                float d = 0.f;
                uint4 kh0, kh1, kh2, kh3;
                for (int ci = 0; ci < n_chunks; ci++){
                    // issue chunk ci+3 (clamped row; slot (ci+3)&3)
                    {
                        int ic = ci + 3;
                        int cc = (ic < n_chunks) ? ic : (n_chunks - 1);
                        const char* src = (const char*)(Kb + (size_t)(rbase + (cc >> 1) * 16) * IN
                                                        + (cc & 1) * 1024) + lane * 16;
                        uint32_t dst = ring32 + (uint32_t)((w4 + (ic & 3)) * 2048) + lane * 16;
                        cp16(dst,        src);
                        cp16(dst +  512, src +  512);
                        cp16(dst + 1024, src + 1024);
                        cp16(dst + 1536, src + 1536);
                        asm volatile("cp.async.commit_group;" ::: "memory");
                    }
                    asm volatile("cp.async.wait_group 3;" ::: "memory");

                    const uint4* sp = (const uint4*)(ring + (size_t)(w4 + (ci & 3)) * 2048
                                                     + lane * 16);
                    uint4 q0 = sp[0], q1 = sp[32], q2 = sp[64], q3 = sp[96];
                    int h = ci & 1;
                    // partial dot over this half-row (fp16 chains of 8, fp32 group sums)
                    float dp;
                    {
                        const uint4* vv = &vr[h * 4];
                        __half2 s0 = __hmul2(*(__half2*)&q0.x, *(__half2*)&vv[0].x);
                        s0 = __hfma2(*(__half2*)&q0.y, *(__half2*)&vv[0].y, s0);
                        s0 = __hfma2(*(__half2*)&q0.z, *(__half2*)&vv[0].z, s0);
                        s0 = __hfma2(*(__half2*)&q0.w, *(__half2*)&vv[0].w, s0);
                        __half2 s1 = __hmul2(*(__half2*)&q1.x, *(__half2*)&vv[1].x);
                        s1 = __hfma2(*(__half2*)&q1.y, *(__half2*)&vv[1].y, s1);
                        s1 = __hfma2(*(__half2*)&q1.z, *(__half2*)&vv[1].z, s1);
                        s1 = __hfma2(*(__half2*)&q1.w, *(__half2*)&vv[1].w, s1);
                        __half2 s2 = __hmul2(*(__half2*)&q2.x, *(__half2*)&vv[2].x);
                        s2 = __hfma2(*(__half2*)&q2.y, *(__half2*)&vv[2].y, s2);
                        s2 = __hfma2(*(__half2*)&q2.z, *(__half2*)&vv[2].z, s2);
                        s2 = __hfma2(*(__half2*)&q2.w, *(__half2*)&vv[2].w, s2);
                        __half2 s3 = __hmul2(*(__half2*)&q3.x, *(__half2*)&vv[3].x);
                        s3 = __hfma2(*(__half2*)&q3.y, *(__half2*)&vv[3].y, s3);
                        s3 = __hfma2(*(__half2*)&q3.z, *(__half2*)&vv[3].z, s3);
                        s3 = __hfma2(*(__half2*)&q3.w, *(__half2*)&vv[3].w, s3);
                        float2 f0 = __half22float2(s0);
                        float2 f1 = __half22float2(s1);
                        float2 f2 = __half22float2(s2);
                        float2 f3 = __half22float2(s3);
                        dp = ((f0.x + f0.y) + (f1.x + f1.y))
                           + ((f2.x + f2.y) + (f3.x + f3.y));
                    }
                    if (h == 0){
                        d = dp;
                        kh0 = q0; kh1 = q1; kh2 = q2; kh3 = q3;
                    } else {
                        d += dp;
                        #pragma unroll
                        for (int off = 16; off; off >>= 1)
                            d += __shfl_xor_sync(0xffffffffu, d, off);
                        float u = 1.0f / d;
                        int row = rbase + (ci >> 1) * 16;
                        if (lane == 0) g_u[ot][seg * IN + row] = u;
                        __half2 u2 = __float2half2_rn(u);
                        acc[ 0] = __hfma2(u2, *(__half2*)&kh0.x, acc[ 0]);
                        acc[ 1] = __hfma2(u2, *(__half2*)&kh0.y, acc[ 1]);
                        acc[ 2] = __hfma2(u2, *(__half2*)&kh0.z, acc[ 2]);
                        acc[ 3] = __hfma2(u2, *(__half2*)&kh0.w, acc[ 3]);
                        acc[ 4] = __hfma2(u2, *(__half2*)&kh1.x, acc[ 4]);
                        acc[ 5] = __hfma2(u2, *(__half2*)&kh1.y, acc[ 5]);
                        acc[ 6] = __hfma2(u2, *(__half2*)&kh1.z, acc[ 6]);
                        acc[ 7] = __hfma2(u2, *(__half2*)&kh1.w, acc[ 7]);
                        acc[ 8] = __hfma2(u2, *(__half2*)&kh2.x, acc[ 8]);
                        acc[ 9] = __hfma2(u2, *(__half2*)&kh2.y, acc[ 9]);
                        acc[10] = __hfma2(u2, *(__half2*)&kh2.z, acc[10]);
                        acc[11] = __hfma2(u2, *(__half2*)&kh2.w, acc[11]);
                        acc[12] = __hfma2(u2, *(__half2*)&kh3.x, acc[12]);
                        acc[13] = __hfma2(u2, *(__half2*)&kh3.y, acc[13]);
                        acc[14] = __hfma2(u2, *(__half2*)&kh3.z, acc[14]);
                        acc[15] = __hfma2(u2, *(__half2*)&kh3.w, acc[15]);
                        acc[16] = __hfma2(u2, *(__half2*)&q0.x, acc[16]);
                        acc[17] = __hfma2(u2, *(__half2*)&q0.y, acc[17]);
                        acc[18] = __hfma2(u2, *(__half2*)&q0.z, acc[18]);
                        acc[19] = __hfma2(u2, *(__half2*)&q0.w, acc[19]);
                        acc[20] = __hfma2(u2, *(__half2*)&q1.x, acc[20]);
                        acc[21] = __hfma2(u2, *(__half2*)&q1.y, acc[21]);
                        acc[22] = __hfma2(u2, *(__half2*)&q1.z, acc[22]);
                        acc[23] = __hfma2(u2, *(__half2*)&q1.w, acc[23]);
                        acc[24] = __hfma2(u2, *(__half2*)&q2.x, acc[24]);
                        acc[25] = __hfma2(u2, *(__half2*)&q2.y, acc[25]);
                        acc[26] = __hfma2(u2, *(__half2*)&q2.z, acc[26]);
                        acc[27] = __hfma2(u2, *(__half2*)&q2.w, acc[27]);
                        acc[28] = __hfma2(u2, *(__half2*)&q3.x, acc[28]);
                        acc[29] = __hfma2(u2, *(__half2*)&q3.y, acc[29]);
                        acc[30] = __hfma2(u2, *(__half2*)&q3.z, acc[30]);
                        acc[31] = __hfma2(u2, *(__half2*)&q3.w, acc[31]);
                    }
                }
                asm volatile("cp.async.wait_group 0;" ::: "memory");
            }

            // write per-warp column partials: position Q=(h*128+j*32+lane), 8 halves each
            #pragma unroll
            for (int t = 0; t < 8; t++){
                int Q = (t >> 2) * 128 + (t & 3) * 32 + lane;
                uint4 o;
                o.x = *(uint32_t*)&acc[t*4+0];
                o.y = *(uint32_t*)&acc[t*4+1];
                o.z = *(uint32_t*)&acc[t*4+2];
                o.w = *(uint32_t*)&acc[t*4+3];
                *(uint4*)&part[warp * IN + Q * 8] = o;
            }
            __syncthreads();

            // cross-warp tree sum + global flush (4 cols per thread)
            {
                int c = tid * 4;
                float s0 = 0.f, s1 = 0.f, s2 = 0.f, s3 = 0.f;
                #pragma unroll
                for (int w = 0; w < 16; w++){
                    uint2 hv = *(const uint2*)&part[w * IN + c];
                    float2 f0 = __half22float2(*(__half2*)&hv.x);
                    float2 f1 = __half22float2(*(__half2*)&hv.y);
                    s0 += f0.x; s1 += f0.y; s2 += f1.x; s3 += f1.y;
                }
                float* Aw = &g_A[ot][(e + 1) % 3][seg * IN];
                atomicAdd(Aw + c + 0, s0);
                atomicAdd(Aw + c + 1, s1);
                atomicAdd(Aw + c + 2, s2);
                atomicAdd(Aw + c + 3, s3);
            }

            // arrive (no wait): wait happens at top of next epoch for this OT
            __threadfence();
            __syncthreads();
            if (tid == 0) atomicAdd(mybar, 1u);
        }
    }

    // wait for both OT barriers to fully drain, then fused vfin
    if (tid == 0){
        volatile unsigned* v1p = &g_bar8[(seg * 2 + 0) * 32];
        volatile unsigned* v2p = &g_bar8[(seg * 2 + 1) * 32];
        unsigned target = (unsigned)ITERS * (unsigned)nbs;
        while (*v1p < target) { __nanosleep(32); }
        while (*v2p < target) { __nanosleep(32); }
    }
    __syncthreads();
    // final A for epoch 49 lives in buf (49+1)%3 == 2
    for (int idx = bis * SKT + tid; idx < 2 * IN; idx += nbs * SKT){
        int o = idx >> 11;
        int r = seg * IN + (idx & 2047);
        g_vfin[o][r] = 1.0f / __ldcg(&g_A[o][2][r]);
    }
}

// ---------------- loss: mean |u1 K1 v1 - u2 K2 v2| --------------------------
__global__ __launch_bounds__(256) void loss_kernel(float* __restrict__ out){
    const uint4* K1 = (const uint4*)g_K1;
    const uint4* K2 = (const uint4*)g_K2;
    const float4* V1 = (const float4*)g_vfin[0];
    const float4* V2 = (const float4*)g_vfin[1];
    int total = KELEMS / 8;
    float s = 0.f;
    for (int idx = blockIdx.x * blockDim.x + threadIdx.x; idx < total;
         idx += gridDim.x * blockDim.x){
        int o8 = idx & 255;          // uint4 (8 halves) within row
        int t  = idx >> 8;
        int i  = t & 2047;
        int b  = t >> 11;
        int row = b * IN + i;
        float u1 = g_u[0][row], u2 = g_u[1][row];
        uint4 k1 = K1[idx], k2 = K2[idx];
        float4 v1a = V1[b * 512 + o8 * 2], v1b = V1[b * 512 + o8 * 2 + 1];
        float4 v2a = V2[b * 512 + o8 * 2], v2b = V2[b * 512 + o8 * 2 + 1];
        float2 a0 = __half22float2(*(__half2*)&k1.x);
        float2 a1 = __half22float2(*(__half2*)&k1.y);
        float2 a2 = __half22float2(*(__half2*)&k1.z);
        float2 a3 = __half22float2(*(__half2*)&k1.w);
        float2 b0 = __half22float2(*(__half2*)&k2.x);
        float2 b1 = __half22float2(*(__half2*)&k2.y);
        float2 b2 = __half22float2(*(__half2*)&k2.z);
        float2 b3 = __half22float2(*(__half2*)&k2.w);
        s += fabsf(u1 * a0.x * v1a.x - u2 * b0.x * v2a.x);
        s += fabsf(u1 * a0.y * v1a.y - u2 * b0.y * v2a.y);
        s += fabsf(u1 * a1.x * v1a.z - u2 * b1.x * v2a.z);
        s += fabsf(u1 * a1.y * v1a.w - u2 * b1.y * v2a.w);
        s += fabsf(u1 * a2.x * v1b.x - u2 * b2.x * v2b.x);
        s += fabsf(u1 * a2.y * v1b.y - u2 * b2.y * v2b.y);
        s += fabsf(u1 * a3.x * v1b.z - u2 * b3.x * v2b.z);
        s += fabsf(u1 * a3.y * v1b.w - u2 * b3.y * v2b.w);
    }
    __shared__ float red[256];
    red[threadIdx.x] = s;
    __syncthreads();
    for (int st = 128; st; st >>= 1){
        if (threadIdx.x < st) red[threadIdx.x] += red[threadIdx.x + st];
        __syncthreads();
    }
    if (threadIdx.x == 0) atomicAdd(out, red[0] * (1.0f / 16777216.0f));
}

// ---------------- launch ----------------------------------------------------
extern "C" void kernel_launch(void* const* d_in, const int* in_sizes, int n_in,
                              void* d_out, int out_size){
    const float* src = (const float*)d_in[0];
    const float* tgt = (const float*)d_in[1];
    const float* gen = (const float*)d_in[2];
    float* out = (float*)d_out;

    int dev = 0;
    cudaGetDevice(&dev);
    int sm = 148;
    cudaDeviceGetAttribute(&sm, cudaDevAttrMultiProcessorCount, dev);

    cudaFuncSetAttribute(sinkhorn_kernel,
                         cudaFuncAttributeMaxDynamicSharedMemorySize,
                         SMEM_TOTAL_BYTES);

    init_kernel<<<32, 256>>>(out);
    profile_pad_kernel<<<1, 32>>>();     // keeps ncu slot on sinkhorn_kernel
    gemm_exp_hmma<<<dim3(IN / 128, IN / 128, 8), 256>>>(src, tgt, gen);
    sinkhorn_kernel<<<sm, SKT, SMEM_TOTAL_BYTES>>>(sm);
    loss_kernel<<<2048, 256>>>(out);
}

// round 13
// speedup vs baseline: 1.2338x; 1.2338x over previous
#include <cuda_runtime.h>
#include <cuda_fp16.h>
#include <cstdint>
#include <cstddef>

#define IN 2048
#define DIM 128
#define NBATCH 4
#define ITERS 50
#define KELEMS (NBATCH*IN*IN)   // 16,777,216 elements

#define SKT 512                  // sinkhorn threads (16 warps)

// dynamic smem: v (4KB) + per-warp partials (16 x 4KB = 64KB)
#define SMEM_V_BYTES 4096
#define SMEM_PART_BYTES (16 * IN * 2)
#define SMEM_TOTAL_BYTES (SMEM_V_BYTES + SMEM_PART_BYTES)

// ---------------- scratch (static device globals: allocation-free) ----------
__device__ __half g_K1[KELEMS];                // K for OT1 (src,tgt)  33.5 MB
__device__ __half g_K2[KELEMS];                // K for OT2 (tgt,gen)  33.5 MB
__device__ float g_A[2][3][NBATCH*IN];         // triple-buffered column accumulators
__device__ float g_u[2][NBATCH*IN];            // final u per OT
__device__ float g_vfin[2][NBATCH*IN];         // final v per OT
__device__ unsigned g_bar8[8 * 32];            // per-(segment,OT) barrier counters

// exp(1 - c) for c in [-1,1]; degree-9 Taylor of exp(t), t=-c, times e.
__device__ __forceinline__ float exp_shift(float c){
    float t = -c;
    float p = 2.7557319e-6f;
    p = fmaf(p, t, 2.4801587e-5f);
    p = fmaf(p, t, 1.9841270e-4f);
    p = fmaf(p, t, 1.3888889e-3f);
    p = fmaf(p, t, 8.3333333e-3f);
    p = fmaf(p, t, 4.1666667e-2f);
    p = fmaf(p, t, 1.6666667e-1f);
    p = fmaf(p, t, 0.5f);
    p = fmaf(p, t, 1.0f);
    p = fmaf(p, t, 1.0f);
    return 2.7182818284f * p;
}

// ---------------- init ------------------------------------------------------
__global__ void init_kernel(float* out){
    int idx = blockIdx.x * blockDim.x + threadIdx.x;
    if (idx == 0) out[0] = 0.0f;
    if (idx < 8 * 32) g_bar8[idx] = 0u;
    if (idx < NBATCH*IN){
        g_A[0][0][idx] = 1.0f;   // epoch 0 reads buf0 => v = ones
        g_A[1][0][idx] = 1.0f;
        g_A[0][1][idx] = 0.0f;   // epoch 0 accumulates into buf1
        g_A[1][1][idx] = 0.0f;
        g_A[0][2][idx] = 0.0f;
        g_A[1][2][idx] = 0.0f;
    }
}

// dummy launch: keeps ncu's -s 5 -c 1 profile window on sinkhorn_kernel
__global__ void profile_pad_kernel(){ }

// ---------------- tensor-core GEMM + exp -> fp16 K --------------------------
#define SA 72   // smem row stride in halves

__global__ __launch_bounds__(256) void gemm_exp_hmma(
        const float* __restrict__ src, const float* __restrict__ tgt,
        const float* __restrict__ gen){
    int ot = blockIdx.z >> 2;
    int b  = blockIdx.z & 3;
    const float* q  = (ot ? tgt : src) + (size_t)b * IN * DIM;
    const float* kk = (ot ? gen : tgt) + (size_t)b * IN * DIM;
    __half* Kout    = (ot ? g_K2 : g_K1) + (size_t)b * IN * IN;
    int i0 = blockIdx.y * 128;
    int o0 = blockIdx.x * 128;

    __shared__ __half As[128 * SA];
    __shared__ __half Bs[128 * SA];

    int tid  = threadIdx.x;
    int lane = tid & 31, warp = tid >> 5;
    int wr = warp >> 2, wc = warp & 3;

    float c[4][4][4];
    #pragma unroll
    for (int mi = 0; mi < 4; mi++)
        #pragma unroll
        for (int ni = 0; ni < 4; ni++)
            #pragma unroll
            for (int j = 0; j < 4; j++) c[mi][ni][j] = 0.f;

    for (int dc = 0; dc < DIM; dc += 64){
        #pragma unroll
        for (int l = 0; l < 8; l++){
            int fidx = tid + 256 * l;       // 0..2047
            int r  = fidx >> 4;
            int f4 = (fidx & 15) << 2;
            float4 va = *(const float4*)(q  + (size_t)(i0 + r) * DIM + dc + f4);
            float4 vb = *(const float4*)(kk + (size_t)(o0 + r) * DIM + dc + f4);
            __half2 a0 = __floats2half2_rn(va.x, va.y);
            __half2 a1 = __floats2half2_rn(va.z, va.w);
            __half2 b0 = __floats2half2_rn(vb.x, vb.y);
            __half2 b1 = __floats2half2_rn(vb.z, vb.w);
            uint2 pa = make_uint2(*(uint32_t*)&a0, *(uint32_t*)&a1);
            uint2 pb = make_uint2(*(uint32_t*)&b0, *(uint32_t*)&b1);
            *(uint2*)&As[r * SA + f4] = pa;
            *(uint2*)&Bs[r * SA + f4] = pb;
        }
        __syncthreads();

        #pragma unroll
        for (int ks = 0; ks < 4; ks++){
            int k0 = ks * 16;
            uint32_t af[4][4], bf[4][2];
            #pragma unroll
            for (int mi = 0; mi < 4; mi++){
                int row = wr * 64 + mi * 16 + (lane & 7) + ((lane >> 3) & 1) * 8;
                int col = k0 + (lane >> 4) * 8;
                uint32_t ad = (uint32_t)__cvta_generic_to_shared(&As[row * SA + col]);
                asm volatile("ldmatrix.sync.aligned.m8n8.x4.shared.b16 {%0,%1,%2,%3}, [%4];"
                    : "=r"(af[mi][0]), "=r"(af[mi][1]), "=r"(af[mi][2]), "=r"(af[mi][3])
                    : "r"(ad));
            }
            #pragma unroll
            for (int ni = 0; ni < 4; ni++){
                int rowb = wc * 32 + ni * 8 + (lane & 7);
                int colb = k0 + ((lane >> 3) & 1) * 8;
                uint32_t ad = (uint32_t)__cvta_generic_to_shared(&Bs[rowb * SA + colb]);
                asm volatile("ldmatrix.sync.aligned.m8n8.x2.shared.b16 {%0,%1}, [%2];"
                    : "=r"(bf[ni][0]), "=r"(bf[ni][1])
                    : "r"(ad));
            }
            #pragma unroll
            for (int mi = 0; mi < 4; mi++)
                #pragma unroll
                for (int ni = 0; ni < 4; ni++){
                    asm volatile(
                        "mma.sync.aligned.m16n8k16.row.col.f32.f16.f16.f32 "
                        "{%0,%1,%2,%3}, {%4,%5,%6,%7}, {%8,%9}, {%0,%1,%2,%3};"
                        : "+f"(c[mi][ni][0]), "+f"(c[mi][ni][1]),
                          "+f"(c[mi][ni][2]), "+f"(c[mi][ni][3])
                        : "r"(af[mi][0]), "r"(af[mi][1]), "r"(af[mi][2]), "r"(af[mi][3]),
                          "r"(bf[ni][0]), "r"(bf[ni][1]));
                }
        }
        __syncthreads();
    }

    // epilogue: exp(1-c), diag = e^-10, write half2 pairs directly
    int rbase = i0 + wr * 64 + (lane >> 2);
    int cbase = o0 + wc * 32 + (lane & 3) * 2;
    #pragma unroll
    for (int mi = 0; mi < 4; mi++){
        #pragma unroll
        for (int ni = 0; ni < 4; ni++){
            int ce = cbase + ni * 8;
            #pragma unroll
            for (int h = 0; h < 2; h++){
                int re = rbase + mi * 16 + h * 8;
                float fx = (re == ce    ) ? 4.5399930e-5f : exp_shift(c[mi][ni][h*2+0]);
                float fy = (re == ce + 1) ? 4.5399930e-5f : exp_shift(c[mi][ni][h*2+1]);
                *(__half2*)(Kout + (size_t)re * IN + ce) = __floats2half2_rn(fx, fy);
            }
        }
    }
}

// ---------------- persistent fused Sinkhorn (register-ring prefetch) --------
// 512 threads, 16 warps, warp-per-row, half-row chunks. 4 rotating register
// buffers (4 uint4 each) + plain __ldcg prefetch at distance 2: 8 LDG.128
// continuously in flight per warp with ~zero extra instructions (no cp.async).
#define H2(x) (*(__half2*)&(x))

#define ISSUE(B0_,B1_,B2_,B3_, cc_) do{ int cc__ = (cc_); \
    if (cc__ < n_chunks){ \
        const uint4* Ks__ = (const uint4*)(Kb + (size_t)(rbase + (cc__ >> 1) * 16) * IN) \
                            + (cc__ & 1) * 128 + lane; \
        B0_ = __ldcg(Ks__); B1_ = __ldcg(Ks__ + 32); \
        B2_ = __ldcg(Ks__ + 64); B3_ = __ldcg(Ks__ + 96); } }while(0)

#define DOTC(dp_, A0,A1,A2,A3, h_) do{ \
    const uint4* Vp__ = V4 + (h_) * 128 + lane; \
    uint4 w0__ = Vp__[0], w1__ = Vp__[32], w2__ = Vp__[64], w3__ = Vp__[96]; \
    __half2 s0__ = __hmul2(H2(A0.x), H2(w0__.x)); \
    s0__ = __hfma2(H2(A0.y), H2(w0__.y), s0__); \
    s0__ = __hfma2(H2(A0.z), H2(w0__.z), s0__); \
    s0__ = __hfma2(H2(A0.w), H2(w0__.w), s0__); \
    __half2 s1__ = __hmul2(H2(A1.x), H2(w1__.x)); \
    s1__ = __hfma2(H2(A1.y), H2(w1__.y), s1__); \
    s1__ = __hfma2(H2(A1.z), H2(w1__.z), s1__); \
    s1__ = __hfma2(H2(A1.w), H2(w1__.w), s1__); \
    __half2 s2__ = __hmul2(H2(A2.x), H2(w2__.x)); \
    s2__ = __hfma2(H2(A2.y), H2(w2__.y), s2__); \
    s2__ = __hfma2(H2(A2.z), H2(w2__.z), s2__); \
    s2__ = __hfma2(H2(A2.w), H2(w2__.w), s2__); \
    __half2 s3__ = __hmul2(H2(A3.x), H2(w3__.x)); \
    s3__ = __hfma2(H2(A3.y), H2(w3__.y), s3__); \
    s3__ = __hfma2(H2(A3.z), H2(w3__.z), s3__); \
    s3__ = __hfma2(H2(A3.w), H2(w3__.w), s3__); \
    float2 f0__ = __half22float2(s0__); \
    float2 f1__ = __half22float2(s1__); \
    float2 f2__ = __half22float2(s2__); \
    float2 f3__ = __half22float2(s3__); \
    dp_ = ((f0__.x + f0__.y) + (f1__.x + f1__.y)) \
        + ((f2__.x + f2__.y) + (f3__.x + f3__.y)); }while(0)

#define ACCP(u2_, A0,A1,A2,A3, b_) do{ \
    acc[(b_)+ 0] = __hfma2(u2_, H2(A0.x), acc[(b_)+ 0]); \
    acc[(b_)+ 1] = __hfma2(u2_, H2(A0.y), acc[(b_)+ 1]); \
    acc[(b_)+ 2] = __hfma2(u2_, H2(A0.z), acc[(b_)+ 2]); \
    acc[(b_)+ 3] = __hfma2(u2_, H2(A0.w), acc[(b_)+ 3]); \
    acc[(b_)+ 4] = __hfma2(u2_, H2(A1.x), acc[(b_)+ 4]); \
    acc[(b_)+ 5] = __hfma2(u2_, H2(A1.y), acc[(b_)+ 5]); \
    acc[(b_)+ 6] = __hfma2(u2_, H2(A1.z), acc[(b_)+ 6]); \
    acc[(b_)+ 7] = __hfma2(u2_, H2(A1.w), acc[(b_)+ 7]); \
    acc[(b_)+ 8] = __hfma2(u2_, H2(A2.x), acc[(b_)+ 8]); \
    acc[(b_)+ 9] = __hfma2(u2_, H2(A2.y), acc[(b_)+ 9]); \
    acc[(b_)+10] = __hfma2(u2_, H2(A2.z), acc[(b_)+10]); \
    acc[(b_)+11] = __hfma2(u2_, H2(A2.w), acc[(b_)+11]); \
    acc[(b_)+12] = __hfma2(u2_, H2(A3.x), acc[(b_)+12]); \
    acc[(b_)+13] = __hfma2(u2_, H2(A3.y), acc[(b_)+13]); \
    acc[(b_)+14] = __hfma2(u2_, H2(A3.z), acc[(b_)+14]); \
    acc[(b_)+15] = __hfma2(u2_, H2(A3.w), acc[(b_)+15]); }while(0)

#define FINISH(dp0_, dp1_, C00,C01,C02,C03, C10,C11,C12,C13, s_) do{ \
    float d__ = (dp0_) + (dp1_); \
    _Pragma("unroll") \
    for (int off__ = 16; off__; off__ >>= 1) \
        d__ += __shfl_xor_sync(0xffffffffu, d__, off__); \
    float u__ = 1.0f / d__; \
    if (lane == 0) g_u[ot][seg * IN + rbase + ((s_) >> 1) * 16] = u__; \
    __half2 u2__ = __float2half2_rn(u__); \
    ACCP(u2__, C00,C01,C02,C03, 0); \
    ACCP(u2__, C10,C11,C12,C13, 16); }while(0)

__global__ __launch_bounds__(SKT, 1) void sinkhorn_kernel(int nblocks){
    extern __shared__ __align__(16) char dynsm[];
    __half* v_sh = (__half*)dynsm;                               // 4 KB
    __half* part = (__half*)(dynsm + SMEM_V_BYTES);              // 64 KB

    int tid  = threadIdx.x;
    int lane = tid & 31, warp = tid >> 5;

    int seg = blockIdx.x & 3;                       // batch segment 0..3
    int bis = blockIdx.x >> 2;
    int nbs = (nblocks - seg + 3) >> 2;             // blocks in this segment
    int r0 = (int)(((long)IN * bis) / nbs);
    int r1 = (int)(((long)IN * (bis + 1)) / nbs);

    int rbase = r0 + warp;                          // always < r1 (>=16 rows/block)
    int nrows = (r1 - rbase + 15) >> 4;
    int n_chunks = nrows * 2;                       // always even, >= 2

    for (int e = 0; e < ITERS; e++){
        for (int ot = 0; ot < 2; ot++){
            unsigned* mybar = &g_bar8[(seg * 2 + ot) * 32];
            // wait for ALL blocks to have flushed epoch e-1 of this OT
            if (e > 0){
                if (tid == 0){
                    volatile unsigned* vb = mybar;
                    unsigned target = (unsigned)e * (unsigned)nbs;
                    while (*vb < target) { __nanosleep(32); }
                }
                __syncthreads();
            }
            const __half* Kb = (ot ? g_K2 : g_K1) + (size_t)seg * IN * IN;
            const float* Ar = &g_A[ot][e % 3][seg * IN];
            float*       Az = &g_A[ot][(e + 2) % 3][seg * IN];
            for (int o = tid; o < IN; o += SKT){
                float v = 1.0f / __ldcg(Ar + o);
                v_sh[o] = __float2half_rn(v);
                Az[o] = 0.0f;                        // idempotent zero for next epoch
            }
            __syncthreads();

            const uint4* V4 = (const uint4*)v_sh;
            __half2 acc[32];
            #pragma unroll
            for (int j = 0; j < 32; j++) acc[j] = __float2half2_rn(0.f);

            // 4 rotating register buffers (chunk c lives in buffer c%4)
            uint4 b00, b01, b02, b03;
            uint4 b10, b11, b12, b13;
            uint4 b20, b21, b22, b23;
            uint4 b30, b31, b32, b33;

            ISSUE(b00,b01,b02,b03, 0);
            ISSUE(b10,b11,b12,b13, 1);

            float dp0;
            int s = 0;
            for (; s + 4 <= n_chunks; s += 4){
                ISSUE(b20,b21,b22,b23, s + 2);
                DOTC(dp0, b00,b01,b02,b03, 0);
                ISSUE(b30,b31,b32,b33, s + 3);
                {
                    float dp1;
                    DOTC(dp1, b10,b11,b12,b13, 1);
                    FINISH(dp0, dp1, b00,b01,b02,b03, b10,b11,b12,b13, s);
                }
                ISSUE(b00,b01,b02,b03, s + 4);
                DOTC(dp0, b20,b21,b22,b23, 0);
                ISSUE(b10,b11,b12,b13, s + 5);
                {
                    float dp1;
                    DOTC(dp1, b30,b31,b32,b33, 1);
                    FINISH(dp0, dp1, b20,b21,b22,b23, b30,b31,b32,b33, s + 2);
                }
            }
            if (s < n_chunks){                       // n_chunks % 4 == 2 remainder
                DOTC(dp0, b00,b01,b02,b03, 0);
                float dp1;
                DOTC(dp1, b10,b11,b12,b13, 1);
                FINISH(dp0, dp1, b00,b01,b02,b03, b10,b11,b12,b13, s);
            }

            // write per-warp column partials: group g=(h*4+j) -> halves h*1024+j*256+lane*8
            #pragma unroll
            for (int t = 0; t < 8; t++){
                int Q = (t >> 2) * 128 + (t & 3) * 32 + lane;
                uint4 o;
                o.x = *(uint32_t*)&acc[t*4+0];
                o.y = *(uint32_t*)&acc[t*4+1];
                o.z = *(uint32_t*)&acc[t*4+2];
                o.w = *(uint32_t*)&acc[t*4+3];
                *(uint4*)&part[warp * IN + Q * 8] = o;
            }
            __syncthreads();

            // cross-warp tree sum + global flush (4 cols per thread)
            {
                int c = tid * 4;
                float s0 = 0.f, s1 = 0.f, s2 = 0.f, s3 = 0.f;
                #pragma unroll
                for (int w = 0; w < 16; w++){
                    uint2 hv = *(const uint2*)&part[w * IN + c];
                    float2 f0 = __half22float2(*(__half2*)&hv.x);
                    float2 f1 = __half22float2(*(__half2*)&hv.y);
                    s0 += f0.x; s1 += f0.y; s2 += f1.x; s3 += f1.y;
                }
                float* Aw = &g_A[ot][(e + 1) % 3][seg * IN];
                atomicAdd(Aw + c + 0, s0);
                atomicAdd(Aw + c + 1, s1);
                atomicAdd(Aw + c + 2, s2);
                atomicAdd(Aw + c + 3, s3);
            }

            // arrive (no wait): wait happens at top of next epoch for this OT
            __threadfence();
            __syncthreads();
            if (tid == 0) atomicAdd(mybar, 1u);
        }
    }

    // wait for both OT barriers to fully drain, then fused vfin
    if (tid == 0){
        volatile unsigned* v1p = &g_bar8[(seg * 2 + 0) * 32];
        volatile unsigned* v2p = &g_bar8[(seg * 2 + 1) * 32];
        unsigned target = (unsigned)ITERS * (unsigned)nbs;
        while (*v1p < target) { __nanosleep(32); }
        while (*v2p < target) { __nanosleep(32); }
    }
    __syncthreads();
    // final A for epoch 49 lives in buf (49+1)%3 == 2
    for (int idx = bis * SKT + tid; idx < 2 * IN; idx += nbs * SKT){
        int o = idx >> 11;
        int r = seg * IN + (idx & 2047);
        g_vfin[o][r] = 1.0f / __ldcg(&g_A[o][2][r]);
    }
}

// ---------------- loss: mean |u1 K1 v1 - u2 K2 v2| --------------------------
__global__ __launch_bounds__(256) void loss_kernel(float* __restrict__ out){
    const uint4* K1 = (const uint4*)g_K1;
    const uint4* K2 = (const uint4*)g_K2;
    const float4* V1 = (const float4*)g_vfin[0];
    const float4* V2 = (const float4*)g_vfin[1];
    int total = KELEMS / 8;
    float s = 0.f;
    for (int idx = blockIdx.x * blockDim.x + threadIdx.x; idx < total;
         idx += gridDim.x * blockDim.x){
        int o8 = idx & 255;          // uint4 (8 halves) within row
        int t  = idx >> 8;
        int i  = t & 2047;
        int b  = t >> 11;
        int row = b * IN + i;
        float u1 = g_u[0][row], u2 = g_u[1][row];
        uint4 k1 = K1[idx], k2 = K2[idx];
        float4 v1a = V1[b * 512 + o8 * 2], v1b = V1[b * 512 + o8 * 2 + 1];
        float4 v2a = V2[b * 512 + o8 * 2], v2b = V2[b * 512 + o8 * 2 + 1];
        float2 a0 = __half22float2(*(__half2*)&k1.x);
        float2 a1 = __half22float2(*(__half2*)&k1.y);
        float2 a2 = __half22float2(*(__half2*)&k1.z);
        float2 a3 = __half22float2(*(__half2*)&k1.w);
        float2 b0 = __half22float2(*(__half2*)&k2.x);
        float2 b1 = __half22float2(*(__half2*)&k2.y);
        float2 b2 = __half22float2(*(__half2*)&k2.z);
        float2 b3 = __half22float2(*(__half2*)&k2.w);
        s += fabsf(u1 * a0.x * v1a.x - u2 * b0.x * v2a.x);
        s += fabsf(u1 * a0.y * v1a.y - u2 * b0.y * v2a.y);
        s += fabsf(u1 * a1.x * v1a.z - u2 * b1.x * v2a.z);
        s += fabsf(u1 * a1.y * v1a.w - u2 * b1.y * v2a.w);
        s += fabsf(u1 * a2.x * v1b.x - u2 * b2.x * v2b.x);
        s += fabsf(u1 * a2.y * v1b.y - u2 * b2.y * v2b.y);
        s += fabsf(u1 * a3.x * v1b.z - u2 * b3.x * v2b.z);
        s += fabsf(u1 * a3.y * v1b.w - u2 * b3.y * v2b.w);
    }
    __shared__ float red[256];
    red[threadIdx.x] = s;
    __syncthreads();
    for (int st = 128; st; st >>= 1){
        if (threadIdx.x < st) red[threadIdx.x] += red[threadIdx.x + st];
        __syncthreads();
    }
    if (threadIdx.x == 0) atomicAdd(out, red[0] * (1.0f / 16777216.0f));
}

// ---------------- launch ----------------------------------------------------
extern "C" void kernel_launch(void* const* d_in, const int* in_sizes, int n_in,
                              void* d_out, int out_size){
    const float* src = (const float*)d_in[0];
    const float* tgt = (const float*)d_in[1];
    const float* gen = (const float*)d_in[2];
    float* out = (float*)d_out;

    int dev = 0;
    cudaGetDevice(&dev);
    int sm = 148;
    cudaDeviceGetAttribute(&sm, cudaDevAttrMultiProcessorCount, dev);

    cudaFuncSetAttribute(sinkhorn_kernel,
                         cudaFuncAttributeMaxDynamicSharedMemorySize,
                         SMEM_TOTAL_BYTES);

    init_kernel<<<32, 256>>>(out);
    profile_pad_kernel<<<1, 32>>>();     // keeps ncu slot on sinkhorn_kernel
    gemm_exp_hmma<<<dim3(IN / 128, IN / 128, 8), 256>>>(src, tgt, gen);
    sinkhorn_kernel<<<sm, SKT, SMEM_TOTAL_BYTES>>>(sm);
    loss_kernel<<<2048, 256>>>(out);
}

// round 14
// speedup vs baseline: 1.3571x; 1.1000x over previous
#include <cuda_runtime.h>
#include <cuda_fp16.h>
#include <cstdint>
#include <cstddef>

#define IN 2048
#define DIM 128
#define NBATCH 4
#define ITERS 50
#define KELEMS (NBATCH*IN*IN)   // 16,777,216 elements

#define SKT 512                  // sinkhorn threads (16 warps)

// dynamic smem: v (4KB) + per-warp partials (16 x 4KB = 64KB)
#define SMEM_V_BYTES 4096
#define SMEM_TOTAL_BYTES (SMEM_V_BYTES + 16 * IN * 2)

#define H2(x) (*(__half2*)&(x))

// ---------------- scratch (static device globals: allocation-free) ----------
__device__ __half g_K1[KELEMS];                // K for OT1 (src,tgt)  33.5 MB
__device__ __half g_K2[KELEMS];                // K for OT2 (tgt,gen)  33.5 MB
__device__ float g_A[2][3][NBATCH*IN];         // triple-buffered column accumulators
__device__ float g_u[2][NBATCH*IN];            // final u per OT
__device__ float g_vfin[2][NBATCH*IN];         // final v per OT
__device__ unsigned g_bar8[8 * 32];            // per-(segment,OT) barrier counters

// exp(1 - c) for c in [-1,1]; degree-9 Taylor of exp(t), t=-c, times e.
__device__ __forceinline__ float exp_shift(float c){
    float t = -c;
    float p = 2.7557319e-6f;
    p = fmaf(p, t, 2.4801587e-5f);
    p = fmaf(p, t, 1.9841270e-4f);
    p = fmaf(p, t, 1.3888889e-3f);
    p = fmaf(p, t, 8.3333333e-3f);
    p = fmaf(p, t, 4.1666667e-2f);
    p = fmaf(p, t, 1.6666667e-1f);
    p = fmaf(p, t, 0.5f);
    p = fmaf(p, t, 1.0f);
    p = fmaf(p, t, 1.0f);
    return 2.7182818284f * p;
}

// ---------------- init ------------------------------------------------------
__global__ void init_kernel(float* out){
    int idx = blockIdx.x * blockDim.x + threadIdx.x;
    if (idx == 0) out[0] = 0.0f;
    if (idx < 8 * 32) g_bar8[idx] = 0u;
    if (idx < NBATCH*IN){
        g_A[0][0][idx] = 1.0f;   // epoch 0 reads buf0 => v = ones
        g_A[1][0][idx] = 1.0f;
        g_A[0][1][idx] = 0.0f;   // epoch 0 accumulates into buf1
        g_A[1][1][idx] = 0.0f;
        g_A[0][2][idx] = 0.0f;
        g_A[1][2][idx] = 0.0f;
    }
}

// dummy launch: keeps ncu's -s 5 -c 1 profile window on sinkhorn_kernel
__global__ void profile_pad_kernel(){ }

// ---------------- tensor-core GEMM + exp -> fp16 K --------------------------
#define SA 72   // smem row stride in halves

__global__ __launch_bounds__(256) void gemm_exp_hmma(
        const float* __restrict__ src, const float* __restrict__ tgt,
        const float* __restrict__ gen){
    int ot = blockIdx.z >> 2;
    int b  = blockIdx.z & 3;
    const float* q  = (ot ? tgt : src) + (size_t)b * IN * DIM;
    const float* kk = (ot ? gen : tgt) + (size_t)b * IN * DIM;
    __half* Kout    = (ot ? g_K2 : g_K1) + (size_t)b * IN * IN;
    int i0 = blockIdx.y * 128;
    int o0 = blockIdx.x * 128;

    __shared__ __half As[128 * SA];
    __shared__ __half Bs[128 * SA];

    int tid  = threadIdx.x;
    int lane = tid & 31, warp = tid >> 5;
    int wr = warp >> 2, wc = warp & 3;

    float c[4][4][4];
    #pragma unroll
    for (int mi = 0; mi < 4; mi++)
        #pragma unroll
        for (int ni = 0; ni < 4; ni++)
            #pragma unroll
            for (int j = 0; j < 4; j++) c[mi][ni][j] = 0.f;

    for (int dc = 0; dc < DIM; dc += 64){
        #pragma unroll
        for (int l = 0; l < 8; l++){
            int fidx = tid + 256 * l;       // 0..2047
            int r  = fidx >> 4;
            int f4 = (fidx & 15) << 2;
            float4 va = *(const float4*)(q  + (size_t)(i0 + r) * DIM + dc + f4);
            float4 vb = *(const float4*)(kk + (size_t)(o0 + r) * DIM + dc + f4);
            __half2 a0 = __floats2half2_rn(va.x, va.y);
            __half2 a1 = __floats2half2_rn(va.z, va.w);
            __half2 b0 = __floats2half2_rn(vb.x, vb.y);
            __half2 b1 = __floats2half2_rn(vb.z, vb.w);
            uint2 pa = make_uint2(*(uint32_t*)&a0, *(uint32_t*)&a1);
            uint2 pb = make_uint2(*(uint32_t*)&b0, *(uint32_t*)&b1);
            *(uint2*)&As[r * SA + f4] = pa;
            *(uint2*)&Bs[r * SA + f4] = pb;
        }
        __syncthreads();

        #pragma unroll
        for (int ks = 0; ks < 4; ks++){
            int k0 = ks * 16;
            uint32_t af[4][4], bf[4][2];
            #pragma unroll
            for (int mi = 0; mi < 4; mi++){
                int row = wr * 64 + mi * 16 + (lane & 7) + ((lane >> 3) & 1) * 8;
                int col = k0 + (lane >> 4) * 8;
                uint32_t ad = (uint32_t)__cvta_generic_to_shared(&As[row * SA + col]);
                asm volatile("ldmatrix.sync.aligned.m8n8.x4.shared.b16 {%0,%1,%2,%3}, [%4];"
                    : "=r"(af[mi][0]), "=r"(af[mi][1]), "=r"(af[mi][2]), "=r"(af[mi][3])
                    : "r"(ad));
            }
            #pragma unroll
            for (int ni = 0; ni < 4; ni++){
                int rowb = wc * 32 + ni * 8 + (lane & 7);
                int colb = k0 + ((lane >> 3) & 1) * 8;
                uint32_t ad = (uint32_t)__cvta_generic_to_shared(&Bs[rowb * SA + colb]);
                asm volatile("ldmatrix.sync.aligned.m8n8.x2.shared.b16 {%0,%1}, [%2];"
                    : "=r"(bf[ni][0]), "=r"(bf[ni][1])
                    : "r"(ad));
            }
            #pragma unroll
            for (int mi = 0; mi < 4; mi++)
                #pragma unroll
                for (int ni = 0; ni < 4; ni++){
                    asm volatile(
                        "mma.sync.aligned.m16n8k16.row.col.f32.f16.f16.f32 "
                        "{%0,%1,%2,%3}, {%4,%5,%6,%7}, {%8,%9}, {%0,%1,%2,%3};"
                        : "+f"(c[mi][ni][0]), "+f"(c[mi][ni][1]),
                          "+f"(c[mi][ni][2]), "+f"(c[mi][ni][3])
                        : "r"(af[mi][0]), "r"(af[mi][1]), "r"(af[mi][2]), "r"(af[mi][3]),
                          "r"(bf[ni][0]), "r"(bf[ni][1]));
                }
        }
        __syncthreads();
    }

    // epilogue: exp(1-c), diag = e^-10, write half2 pairs directly
    int rbase = i0 + wr * 64 + (lane >> 2);
    int cbase = o0 + wc * 32 + (lane & 3) * 2;
    #pragma unroll
    for (int mi = 0; mi < 4; mi++){
        #pragma unroll
        for (int ni = 0; ni < 4; ni++){
            int ce = cbase + ni * 8;
            #pragma unroll
            for (int h = 0; h < 2; h++){
                int re = rbase + mi * 16 + h * 8;
                float fx = (re == ce    ) ? 4.5399930e-5f : exp_shift(c[mi][ni][h*2+0]);
                float fy = (re == ce + 1) ? 4.5399930e-5f : exp_shift(c[mi][ni][h*2+1]);
                *(__half2*)(Kout + (size_t)re * IN + ce) = __floats2half2_rn(fx, fy);
            }
        }
    }
}

// ---------------- persistent fused Sinkhorn (lean-dot single pass) ----------
// R9 structure (best: 512 thr, warp-per-row, batch-8 LDG) with the fma-pipe
// work cut ~1.5x: dot = 4 persistent half2 HFMA2 chains (1 op per component),
// v in registers all epoch (no LDS in the row loop).
__global__ __launch_bounds__(SKT, 1) void sinkhorn_kernel(int nblocks){
    extern __shared__ __align__(16) char dynsm[];
    __half* v_sh = (__half*)dynsm;                       // 4 KB
    __half* part = (__half*)(dynsm + SMEM_V_BYTES);      // [16][2048] halves

    int tid  = threadIdx.x;
    int lane = tid & 31, warp = tid >> 5;

    int seg = blockIdx.x & 3;                       // batch segment 0..3
    int bis = blockIdx.x >> 2;
    int nbs = (nblocks - seg + 3) >> 2;             // blocks in this segment
    int r0 = (int)(((long)IN * bis) / nbs);
    int r1 = (int)(((long)IN * (bis + 1)) / nbs);

    for (int e = 0; e < ITERS; e++){
        for (int ot = 0; ot < 2; ot++){
            unsigned* mybar = &g_bar8[(seg * 2 + ot) * 32];
            // wait for ALL blocks to have flushed epoch e-1 of this OT
            if (e > 0){
                if (tid == 0){
                    volatile unsigned* vb = mybar;
                    unsigned target = (unsigned)e * (unsigned)nbs;
                    while (*vb < target) { __nanosleep(32); }
                }
                __syncthreads();
            }
            const __half* Kb = (ot ? g_K2 : g_K1) + (size_t)seg * IN * IN;
            const float* Ar = &g_A[ot][e % 3][seg * IN];
            float*       Az = &g_A[ot][(e + 2) % 3][seg * IN];
            for (int o = tid; o < IN; o += SKT){
                float v = 1.0f / __ldcg(Ar + o);
                v_sh[o] = __float2half_rn(v);
                Az[o] = 0.0f;                        // idempotent zero for next epoch
            }
            __syncthreads();

            // v -> registers for the whole epoch
            const uint4* V4 = (const uint4*)v_sh;
            uint4 vr[8];
            #pragma unroll
            for (int j = 0; j < 8; j++) vr[j] = V4[j * 32 + lane];

            __half2 acc[32];
            #pragma unroll
            for (int j = 0; j < 32; j++) acc[j] = __float2half2_rn(0.f);

            for (int row = r0 + warp; row < r1; row += 16){
                const uint4* Kr = (const uint4*)(Kb + (size_t)row * IN);
                uint4 k[8];
                #pragma unroll
                for (int j = 0; j < 8; j++) k[j] = __ldcg(&Kr[j * 32 + lane]);

                // dot via 4 persistent half2 chains (8-deep each per half-lane)
                __half2 c0 = __hmul2(H2(k[0].x), H2(vr[0].x));
                __half2 c1 = __hmul2(H2(k[0].y), H2(vr[0].y));
                __half2 c2 = __hmul2(H2(k[0].z), H2(vr[0].z));
                __half2 c3 = __hmul2(H2(k[0].w), H2(vr[0].w));
                #pragma unroll
                for (int j = 1; j < 8; j++){
                    c0 = __hfma2(H2(k[j].x), H2(vr[j].x), c0);
                    c1 = __hfma2(H2(k[j].y), H2(vr[j].y), c1);
                    c2 = __hfma2(H2(k[j].z), H2(vr[j].z), c2);
                    c3 = __hfma2(H2(k[j].w), H2(vr[j].w), c3);
                }
                float2 f0 = __half22float2(c0);
                float2 f1 = __half22float2(c1);
                float2 f2 = __half22float2(c2);
                float2 f3 = __half22float2(c3);
                float dot = ((f0.x + f0.y) + (f1.x + f1.y))
                          + ((f2.x + f2.y) + (f3.x + f3.y));
                #pragma unroll
                for (int off = 16; off; off >>= 1)
                    dot += __shfl_xor_sync(0xffffffffu, dot, off);
                float u = 1.0f / dot;            // all lanes have it
                if (lane == 0) g_u[ot][seg * IN + row] = u;
                __half2 u2 = __float2half2_rn(u);
                #pragma unroll
                for (int j = 0; j < 8; j++){
                    acc[j*4+0] = __hfma2(u2, H2(k[j].x), acc[j*4+0]);
                    acc[j*4+1] = __hfma2(u2, H2(k[j].y), acc[j*4+1]);
                    acc[j*4+2] = __hfma2(u2, H2(k[j].z), acc[j*4+2]);
                    acc[j*4+3] = __hfma2(u2, H2(k[j].w), acc[j*4+3]);
                }
            }
            // ---- write per-warp column partials to smem ----
            #pragma unroll
            for (int j = 0; j < 8; j++){
                uint4 o;
                o.x = *(uint32_t*)&acc[j*4+0];
                o.y = *(uint32_t*)&acc[j*4+1];
                o.z = *(uint32_t*)&acc[j*4+2];
                o.w = *(uint32_t*)&acc[j*4+3];
                *(uint4*)&part[warp * IN + j * 256 + lane * 8] = o;
            }
            __syncthreads();

            // ---- cross-warp tree sum + global flush (4 cols per thread) ----
            {
                int c = tid * 4;
                float s0 = 0.f, s1 = 0.f, s2 = 0.f, s3 = 0.f;
                #pragma unroll
                for (int w = 0; w < 16; w++){
                    uint2 hv = *(const uint2*)&part[w * IN + c];
                    float2 f0 = __half22float2(*(__half2*)&hv.x);
                    float2 f1 = __half22float2(*(__half2*)&hv.y);
                    s0 += f0.x; s1 += f0.y; s2 += f1.x; s3 += f1.y;
                }
                float* Aw = &g_A[ot][(e + 1) % 3][seg * IN];
                atomicAdd(Aw + c + 0, s0);
                atomicAdd(Aw + c + 1, s1);
                atomicAdd(Aw + c + 2, s2);
                atomicAdd(Aw + c + 3, s3);
            }

            // arrive (no wait): wait happens at top of next epoch for this OT
            __threadfence();
            __syncthreads();
            if (tid == 0) atomicAdd(mybar, 1u);
        }
    }

    // wait for both OT barriers to fully drain, then fused vfin
    if (tid == 0){
        volatile unsigned* v1p = &g_bar8[(seg * 2 + 0) * 32];
        volatile unsigned* v2p = &g_bar8[(seg * 2 + 1) * 32];
        unsigned target = (unsigned)ITERS * (unsigned)nbs;
        while (*v1p < target) { __nanosleep(32); }
        while (*v2p < target) { __nanosleep(32); }
    }
    __syncthreads();
    // final A for epoch 49 lives in buf (49+1)%3 == 2
    for (int idx = bis * SKT + tid; idx < 2 * IN; idx += nbs * SKT){
        int o = idx >> 11;
        int r = seg * IN + (idx & 2047);
        g_vfin[o][r] = 1.0f / __ldcg(&g_A[o][2][r]);
    }
}

// ---------------- loss: mean |u1 K1 v1 - u2 K2 v2| --------------------------
__global__ __launch_bounds__(256) void loss_kernel(float* __restrict__ out){
    const uint4* K1 = (const uint4*)g_K1;
    const uint4* K2 = (const uint4*)g_K2;
    const float4* V1 = (const float4*)g_vfin[0];
    const float4* V2 = (const float4*)g_vfin[1];
    int total = KELEMS / 8;
    float s = 0.f;
    for (int idx = blockIdx.x * blockDim.x + threadIdx.x; idx < total;
         idx += gridDim.x * blockDim.x){
        int o8 = idx & 255;          // uint4 (8 halves) within row
        int t  = idx >> 8;
        int i  = t & 2047;
        int b  = t >> 11;
        int row = b * IN + i;
        float u1 = g_u[0][row], u2 = g_u[1][row];
        uint4 k1 = K1[idx], k2 = K2[idx];
        float4 v1a = V1[b * 512 + o8 * 2], v1b = V1[b * 512 + o8 * 2 + 1];
        float4 v2a = V2[b * 512 + o8 * 2], v2b = V2[b * 512 + o8 * 2 + 1];
        float2 a0 = __half22float2(*(__half2*)&k1.x);
        float2 a1 = __half22float2(*(__half2*)&k1.y);
        float2 a2 = __half22float2(*(__half2*)&k1.z);
        float2 a3 = __half22float2(*(__half2*)&k1.w);
        float2 b0 = __half22float2(*(__half2*)&k2.x);
        float2 b1 = __half22float2(*(__half2*)&k2.y);
        float2 b2 = __half22float2(*(__half2*)&k2.z);
        float2 b3 = __half22float2(*(__half2*)&k2.w);
        s += fabsf(u1 * a0.x * v1a.x - u2 * b0.x * v2a.x);
        s += fabsf(u1 * a0.y * v1a.y - u2 * b0.y * v2a.y);
        s += fabsf(u1 * a1.x * v1a.z - u2 * b1.x * v2a.z);
        s += fabsf(u1 * a1.y * v1a.w - u2 * b1.y * v2a.w);
        s += fabsf(u1 * a2.x * v1b.x - u2 * b2.x * v2b.x);
        s += fabsf(u1 * a2.y * v1b.y - u2 * b2.y * v2b.y);
        s += fabsf(u1 * a3.x * v1b.z - u2 * b3.x * v2b.z);
        s += fabsf(u1 * a3.y * v1b.w - u2 * b3.y * v2b.w);
    }
    __shared__ float red[256];
    red[threadIdx.x] = s;
    __syncthreads();
    for (int st = 128; st; st >>= 1){
        if (threadIdx.x < st) red[threadIdx.x] += red[threadIdx.x + st];
        __syncthreads();
    }
    if (threadIdx.x == 0) atomicAdd(out, red[0] * (1.0f / 16777216.0f));
}

// ---------------- launch ----------------------------------------------------
extern "C" void kernel_launch(void* const* d_in, const int* in_sizes, int n_in,
                              void* d_out, int out_size){
    const float* src = (const float*)d_in[0];
    const float* tgt = (const float*)d_in[1];
    const float* gen = (const float*)d_in[2];
    float* out = (float*)d_out;

    int dev = 0;
    cudaGetDevice(&dev);
    int sm = 148;
    cudaDeviceGetAttribute(&sm, cudaDevAttrMultiProcessorCount, dev);

    cudaFuncSetAttribute(sinkhorn_kernel,
                         cudaFuncAttributeMaxDynamicSharedMemorySize,
                         SMEM_TOTAL_BYTES);

    init_kernel<<<32, 256>>>(out);
    profile_pad_kernel<<<1, 32>>>();     // keeps ncu slot on sinkhorn_kernel
    gemm_exp_hmma<<<dim3(IN / 128, IN / 128, 8), 256>>>(src, tgt, gen);
    sinkhorn_kernel<<<sm, SKT, SMEM_TOTAL_BYTES>>>(sm);
    loss_kernel<<<2048, 256>>>(out);
}